// round 3
// baseline (speedup 1.0000x reference)
#include <cuda_runtime.h>

#define BQ 4
#define LQ 2048
#define DM 64
#define ED 128
#define NQ 32
#define DCV 16
#define DTR 4
#define RQ 68            // DTR + 2*N
#define EPSQ 1e-5f
#define LOG2EF 1.4426950408889634f

#define CH 64            // steps per chunk
#define NCH 32           // chunks (CH*NCH = LQ)
#define EG 16            // e-channels per scan block

// ---------------- scratch (device globals; no allocation allowed) ----------------
__device__ float  g_h[BQ * LQ * DM];             // residual stream
__device__ float  g_xz[BQ * LQ * 2 * ED];        // in_proj output
__device__ float2 g_dx[BQ * LQ * ED];            // {delta, delta*xc}
__device__ float2 g_gate[BQ * LQ * ED];          // {silu(z), Dp*xc*silu(z)}
__device__ float2 g_bc[BQ * LQ * NQ];            // {B, C}
__device__ float  g_yout[BQ * ED * LQ];          // gated scan output, (B,E,L)
__device__ float2 g_carry[BQ * ED * NCH * NQ];   // {h_final, P} per (b,e,chunk,n)
__device__ float  g_hstart[BQ * ED * NCH * NQ];  // exclusive prefix h per (b,e,chunk,n)

__device__ __forceinline__ float ex2(float x) {
    float r; asm("ex2.approx.ftz.f32 %0, %1;" : "=f"(r) : "f"(x)); return r;
}

// ================= K1: rmsnorm + in_proj =================
__global__ void __launch_bounds__(256) k1_rms_inproj(
    const float* __restrict__ hin,
    const float* __restrict__ inw,   // (256, 64)
    const float* __restrict__ inb,   // (256)
    const float* __restrict__ nw)    // (64)
{
    __shared__ float s_nrow[32][68];

    int b  = blockIdx.x >> 6;
    int l0 = (blockIdx.x & 63) << 5;
    int tid = threadIdx.x;
    int lane = tid & 31, wid = tid >> 5;

    #pragma unroll
    for (int il = 0; il < 4; ++il) {
        int l = wid * 4 + il;
        const float* hr = hin + ((size_t)(b * LQ + l0 + l)) * DM;
        float v0 = hr[lane], v1 = hr[lane + 32];
        float ss = v0 * v0 + v1 * v1;
        #pragma unroll
        for (int s = 16; s; s >>= 1) ss += __shfl_xor_sync(~0u, ss, s);
        float r = rsqrtf(ss * (1.0f / DM) + EPSQ);
        s_nrow[l][lane]      = v0 * r * nw[lane];
        s_nrow[l][lane + 32] = v1 * r * nw[lane + 32];
    }
    __syncthreads();

    int c = tid;
    float acc[32];
    #pragma unroll
    for (int l = 0; l < 32; ++l) acc[l] = 0.f;

    const float4* w4p = (const float4*)inw + c * 16;
    #pragma unroll 1
    for (int k4 = 0; k4 < 16; ++k4) {
        float4 w = __ldg(&w4p[k4]);
        #pragma unroll
        for (int l = 0; l < 32; ++l) {
            float4 s = *(const float4*)&s_nrow[l][k4 * 4];
            acc[l] += w.x * s.x + w.y * s.y + w.z * s.z + w.w * s.w;
        }
    }
    float bb = inb[c];
    float* xzp = g_xz + ((size_t)(b * LQ + l0)) * 256 + c;
    #pragma unroll
    for (int l = 0; l < 32; ++l) xzp[(size_t)l * 256] = acc[l] + bb;
}

// ================= K2: dwconv + silu + xproj + dtproj + softplus + packing =================
#define K2_SMEM_FLOATS 21568
#define K2_SMEM_BYTES  (K2_SMEM_FLOATS * 4)

__global__ void __launch_bounds__(256) k2_conv_xproj(
    const float* __restrict__ convw,
    const float* __restrict__ convb,
    const float* __restrict__ xprojw,
    const float* __restrict__ dtw,
    const float* __restrict__ dtb,
    const float* __restrict__ Dpw)
{
    extern __shared__ float sm[];
    float* s_xin   = sm;
    float* s_convw = sm + 79 * 128;
    float* s_xw    = sm;
    float* s_dbc   = sm + 68 * 128;
    float* s_xc    = sm + 13120;

    int b  = blockIdx.x >> 5;
    int l0 = (blockIdx.x & 31) << 6;
    int tid = threadIdx.x;

    for (int i = tid; i < 128 * 16; i += 256) s_convw[i] = convw[i];
    for (int i = tid; i < 79 * 128; i += 256) {
        int r = i >> 7, ch = i & 127;
        int l = l0 - 15 + r;
        s_xin[i] = (l >= 0) ? g_xz[((size_t)(b * LQ + l)) * 256 + ch] : 0.f;
    }
    __syncthreads();

    for (int i = tid; i < 64 * 128; i += 256) {
        int l = i >> 7, ch = i & 127;
        float acc = convb[ch];
        #pragma unroll
        for (int j = 0; j < DCV; ++j)
            acc += s_convw[ch * DCV + j] * s_xin[(l + j) * 128 + ch];
        float sg = 1.f / (1.f + __expf(-acc));
        s_xc[l * 132 + ch] = acc * sg;
    }
    __syncthreads();

    for (int i = tid; i < 68 * 128; i += 256) s_xw[i] = xprojw[i];
    __syncthreads();

    {
        int l = tid & 63, rg = tid >> 6;
        float acc[17];
        #pragma unroll
        for (int r = 0; r < 17; ++r) acc[r] = 0.f;
        const float4* xc4 = (const float4*)(s_xc + l * 132);
        #pragma unroll 1
        for (int kc = 0; kc < 4; ++kc) {
            float4 xr[8];
            #pragma unroll
            for (int q = 0; q < 8; ++q) xr[q] = xc4[kc * 8 + q];
            #pragma unroll
            for (int rr = 0; rr < 17; ++rr) {
                const float4* w4 = (const float4*)(s_xw + (rg * 17 + rr) * 128 + kc * 32);
                float a = acc[rr];
                #pragma unroll
                for (int q = 0; q < 8; ++q) {
                    float4 w = w4[q];
                    a += w.x * xr[q].x + w.y * xr[q].y + w.z * xr[q].z + w.w * xr[q].w;
                }
                acc[rr] = a;
            }
        }
        #pragma unroll
        for (int rr = 0; rr < 17; ++rr) s_dbc[l * 69 + rg * 17 + rr] = acc[rr];
    }
    __syncthreads();

    for (int i = tid; i < 64 * 128; i += 256) {
        int l = i >> 7, e = i & 127;
        const float* dr = s_dbc + l * 69;
        float4 wv = *(const float4*)(dtw + e * 4);
        float v = dr[0] * wv.x + dr[1] * wv.y + dr[2] * wv.z + dr[3] * wv.w + dtb[e];
        float delta = (v > 20.f) ? v : log1pf(__expf(v));
        float xcv = s_xc[l * 132 + e];
        float z  = g_xz[((size_t)(b * LQ + l0 + l)) * 256 + 128 + e];
        float gz = z / (1.f + __expf(-z));
        size_t oidx = ((size_t)(b * LQ + l0 + l)) * 128 + e;
        g_dx[oidx]   = make_float2(delta, delta * xcv);
        g_gate[oidx] = make_float2(gz, Dpw[e] * xcv * gz);
    }
    for (int i = tid; i < 64 * 32; i += 256) {
        int l = i >> 5, n = i & 31;
        const float* dr = s_dbc + l * 69;
        g_bc[((size_t)(b * LQ + l0 + l)) * 32 + n] = make_float2(dr[DTR + n], dr[DTR + NQ + n]);
    }
}

// ================= K3a: local chunk scan (carry out) =================
// grid: b(4) x chunk(32) x egroup(8) = 1024 blocks; 512 threads = 16 warps = 16 e's.
// B/C chunk staged in smem once per block, shared across 16 e-warps.
__global__ void __launch_bounds__(512) k3a_scan_local(const float* __restrict__ Alog)
{
    __shared__ float2 s_bc[CH * NQ];   // 16 KB

    int eg = blockIdx.x & 7;
    int c  = (blockIdx.x >> 3) & 31;
    int b  = blockIdx.x >> 8;
    int tid = threadIdx.x, lane = tid & 31, w = tid >> 5;
    int e = eg * EG + w;

    const float2* bsrc = g_bc + ((size_t)(b * LQ) + c * CH) * NQ;
    for (int i = tid; i < CH * NQ; i += 512) s_bc[i] = bsrc[i];
    __syncthreads();

    float aA = -__expf(Alog[e * NQ + lane]) * LOG2EF;
    const float2* dxp = g_dx + ((size_t)(b * LQ) + c * CH) * ED + e;

    float h = 0.f, P = 1.f;
    #pragma unroll 8
    for (int j = 0; j < CH; ++j) {
        float2 m = __ldg(dxp + (size_t)j * ED);   // broadcast
        float2 wv = s_bc[j * NQ + lane];
        float dA = ex2(m.x * aA);
        h = fmaf(dA, h, m.y * wv.x);
        P *= dA;
    }
    g_carry[(((size_t)(b * ED + e)) * NCH + c) * NQ + lane] = make_float2(h, P);
}

// ================= K3b: cross-chunk exclusive combine =================
// thread = (b,e,n): serial over 32 chunks. grid 64 x 256 = 16384 threads.
__global__ void __launch_bounds__(256) k3b_combine()
{
    int idx = blockIdx.x * 256 + threadIdx.x;
    size_t base = (size_t)(idx >> 5) * NCH * NQ + (idx & 31);
    const float2* cp = g_carry + base;
    float* hp = g_hstart + base;
    float hs = 0.f;
    #pragma unroll
    for (int c = 0; c < NCH; ++c) {
        float2 v = cp[(size_t)c * NQ];
        hp[(size_t)c * NQ] = hs;
        hs = fmaf(v.y, hs, v.x);
    }
}

// ================= K3c: rescan with true h_start, reduce, gate =================
__global__ void __launch_bounds__(512) k3c_scan_out(const float* __restrict__ Alog)
{
    __shared__ float2 s_bc[CH * NQ];

    int eg = blockIdx.x & 7;
    int c  = (blockIdx.x >> 3) & 31;
    int b  = blockIdx.x >> 8;
    int tid = threadIdx.x, lane = tid & 31, w = tid >> 5;
    int e = eg * EG + w;

    const float2* bsrc = g_bc + ((size_t)(b * LQ) + c * CH) * NQ;
    for (int i = tid; i < CH * NQ; i += 512) s_bc[i] = bsrc[i];
    __syncthreads();

    float aA = -__expf(Alog[e * NQ + lane]) * LOG2EF;
    const float2* dxp = g_dx   + ((size_t)(b * LQ) + c * CH) * ED + e;
    const float2* gtp = g_gate + ((size_t)(b * LQ) + c * CH) * ED + e;
    float* yp = g_yout + ((size_t)(b * ED + e)) * LQ + c * CH;

    float h = g_hstart[(((size_t)(b * ED + e)) * NCH + c) * NQ + lane];

    for (int t0 = 0; t0 < CH; t0 += 32) {
        float ysum = 0.f;
        #pragma unroll
        for (int j = 0; j < 32; ++j) {
            float2 m = __ldg(dxp + (size_t)(t0 + j) * ED);
            float2 wv = s_bc[(t0 + j) * NQ + lane];
            float dA = ex2(m.x * aA);
            h = fmaf(dA, h, m.y * wv.x);
            float yv = h * wv.y;
            #pragma unroll
            for (int s = 16; s; s >>= 1) yv += __shfl_xor_sync(~0u, yv, s);
            if (j == lane) ysum = yv;
        }
        float2 g = __ldg(gtp + (size_t)(t0 + lane) * ED);
        yp[t0 + lane] = fmaf(ysum, g.x, g.y);
    }
}

// ================= K4: out_proj + residual =================
// grid: B * (L/16) = 512 blocks, 256 threads. Thread = (d, l-group of 4).
// Weights streamed via LDG.128 along each d-row (L1-resident); y transposed in smem.
__global__ void __launch_bounds__(256) k4_outproj(
    const float* __restrict__ ow,   // (64, 128)
    const float* __restrict__ ob,   // (64)
    const float* __restrict__ hin,
    float* __restrict__ hout)
{
    __shared__ float s_y[16 * 132];  // [l][k] padded (132 mult of 4 for LDS.128)

    int b  = blockIdx.x >> 7;
    int l0 = (blockIdx.x & 127) << 4;
    int tid = threadIdx.x;

    for (int i = tid; i < 128 * 16; i += 256) {
        int e = i >> 4, lc = i & 15;
        s_y[lc * 132 + e] = g_yout[((size_t)(b * 128 + e)) * LQ + l0 + lc];
    }
    __syncthreads();

    int d = tid & 63, lg = tid >> 6;   // 4 l's per thread
    float acc[4][4];                    // [li][partial by k-phase folded] -> use [li]
    float a0 = 0.f, a1 = 0.f, a2 = 0.f, a3 = 0.f;
    (void)acc;

    const float4* wp = (const float4*)(ow + d * 128);
    const float4* y0 = (const float4*)(s_y + (lg * 4 + 0) * 132);
    const float4* y1 = (const float4*)(s_y + (lg * 4 + 1) * 132);
    const float4* y2 = (const float4*)(s_y + (lg * 4 + 2) * 132);
    const float4* y3 = (const float4*)(s_y + (lg * 4 + 3) * 132);

    #pragma unroll 8
    for (int k4 = 0; k4 < 32; ++k4) {
        float4 w = __ldg(&wp[k4]);
        float4 v0 = y0[k4], v1 = y1[k4], v2 = y2[k4], v3 = y3[k4];
        a0 += w.x * v0.x + w.y * v0.y + w.z * v0.z + w.w * v0.w;
        a1 += w.x * v1.x + w.y * v1.y + w.z * v1.z + w.w * v1.w;
        a2 += w.x * v2.x + w.y * v2.y + w.z * v2.z + w.w * v2.w;
        a3 += w.x * v3.x + w.y * v3.y + w.z * v3.z + w.w * v3.w;
    }

    float bias = ob[d];
    float r0 = a0, r1 = a1, r2 = a2, r3 = a3;
    size_t rbase = ((size_t)(b * LQ + l0 + lg * 4)) * DM + d;
    hout[rbase + 0 * DM] = hin[rbase + 0 * DM] + bias + r0;
    hout[rbase + 1 * DM] = hin[rbase + 1 * DM] + bias + r1;
    hout[rbase + 2 * DM] = hin[rbase + 2 * DM] + bias + r2;
    hout[rbase + 3 * DM] = hin[rbase + 3 * DM] + bias + r3;
}

// ================= final classifier head =================
__global__ void __launch_bounds__(128) k_final(
    const float* __restrict__ fcw, const float* __restrict__ fcb, float* __restrict__ out)
{
    int b = threadIdx.x >> 5, lane = threadIdx.x & 31;
    float s = 0.f;
    #pragma unroll
    for (int j = 0; j < 4; ++j) {
        int e = lane + 32 * j;
        s += g_yout[((size_t)(b * 128 + e)) * LQ + (LQ - 1)] * fcw[e];
    }
    #pragma unroll
    for (int d = 16; d; d >>= 1) s += __shfl_xor_sync(~0u, s, d);
    if (lane == 0) out[b] = s + fcb[0];
}

// ================= launch =================
extern "C" void kernel_launch(void* const* d_in, const int* in_sizes, int n_in,
                              void* d_out, int out_size)
{
    const float* x        = (const float*)d_in[0];
    const float* in_w     = (const float*)d_in[1];
    const float* in_b     = (const float*)d_in[2];
    const float* conv_w   = (const float*)d_in[3];
    const float* conv_b   = (const float*)d_in[4];
    const float* xproj_w  = (const float*)d_in[5];
    const float* dtproj_w = (const float*)d_in[6];
    const float* dtproj_b = (const float*)d_in[7];
    const float* A_log    = (const float*)d_in[8];
    const float* Dp       = (const float*)d_in[9];
    const float* outp_w   = (const float*)d_in[10];
    const float* outp_b   = (const float*)d_in[11];
    const float* norm_w   = (const float*)d_in[12];
    const float* fc_w     = (const float*)d_in[13];
    const float* fc_b     = (const float*)d_in[14];
    float* out = (float*)d_out;

    (void)in_sizes; (void)n_in; (void)out_size;

    cudaFuncSetAttribute(k2_conv_xproj, cudaFuncAttributeMaxDynamicSharedMemorySize, K2_SMEM_BYTES);

    float* gh = nullptr;
    cudaGetSymbolAddress((void**)&gh, g_h);

    for (int i = 0; i < 4; ++i) {
        const float* hin = (i == 0) ? x : gh;
        k1_rms_inproj<<<256, 256>>>(hin,
                                    in_w + (size_t)i * 2 * ED * DM,
                                    in_b + (size_t)i * 2 * ED,
                                    norm_w + (size_t)i * DM);
        k2_conv_xproj<<<128, 256, K2_SMEM_BYTES>>>(
            conv_w   + (size_t)i * ED * DCV,
            conv_b   + (size_t)i * ED,
            xproj_w  + (size_t)i * RQ * ED,
            dtproj_w + (size_t)i * ED * DTR,
            dtproj_b + (size_t)i * ED,
            Dp       + (size_t)i * ED);
        const float* Al = A_log + (size_t)i * ED * NQ;
        k3a_scan_local<<<1024, 512>>>(Al);
        k3b_combine<<<64, 256>>>();
        k3c_scan_out<<<1024, 512>>>(Al);
        if (i < 3)
            k4_outproj<<<512, 256>>>(
                outp_w + (size_t)i * DM * ED,
                outp_b + (size_t)i * DM,
                hin, gh);
    }
    k_final<<<1, 128>>>(fc_w, fc_b, out);
}

// round 4
// speedup vs baseline: 1.1555x; 1.1555x over previous
#include <cuda_runtime.h>

#define BQ 4
#define LQ 2048
#define DM 64
#define ED 128
#define NQ 32
#define DCV 16
#define DTR 4
#define RQ 68            // DTR + 2*N
#define EPSQ 1e-5f
#define LOG2EF 1.4426950408889634f

#define CH 64            // steps per chunk
#define NCH 32           // chunks (CH*NCH = LQ)
#define EG 16            // e-channels per scan block

// ---------------- scratch (device globals; no allocation allowed) ----------------
__device__ float  g_h[BQ * LQ * DM];             // residual stream
__device__ float  g_xz[BQ * LQ * 2 * ED];        // in_proj output
__device__ float2 g_dx[BQ * LQ * ED];            // {delta, delta*xc}
__device__ float2 g_gate[BQ * LQ * ED];          // {silu(z), Dp*xc*silu(z)}
__device__ float  g_bB[BQ * LQ * NQ];            // B
__device__ float  g_bC[BQ * LQ * NQ];            // C
__device__ float  g_yout[BQ * ED * LQ];          // gated scan output, (B,E,L)
__device__ float2 g_carry[BQ * ED * NCH * NQ];   // {h_final, P} per (b,e,chunk,n)

__device__ __forceinline__ float ex2(float x) {
    float r; asm("ex2.approx.ftz.f32 %0, %1;" : "=f"(r) : "f"(x)); return r;
}

// ================= K1: rmsnorm + in_proj =================
// grid: B * (L/16) = 512 blocks, 256 threads. Each block: 16 timesteps.
__global__ void __launch_bounds__(256) k1_rms_inproj(
    const float* __restrict__ hin,
    const float* __restrict__ inw,   // (256, 64)
    const float* __restrict__ inb,   // (256)
    const float* __restrict__ nw)    // (64)
{
    __shared__ float s_nrow[16][68];

    int b  = blockIdx.x >> 7;
    int l0 = (blockIdx.x & 127) << 4;
    int tid = threadIdx.x;
    int lane = tid & 31, wid = tid >> 5;

    // rmsnorm: 8 warps x 2 rows
    #pragma unroll
    for (int il = 0; il < 2; ++il) {
        int l = wid * 2 + il;
        const float* hr = hin + ((size_t)(b * LQ + l0 + l)) * DM;
        float v0 = hr[lane], v1 = hr[lane + 32];
        float ss = v0 * v0 + v1 * v1;
        #pragma unroll
        for (int s = 16; s; s >>= 1) ss += __shfl_xor_sync(~0u, ss, s);
        float r = rsqrtf(ss * (1.0f / DM) + EPSQ);
        s_nrow[l][lane]      = v0 * r * nw[lane];
        s_nrow[l][lane + 32] = v1 * r * nw[lane + 32];
    }
    __syncthreads();

    // in_proj: thread = output channel c; 16 l positions in regs
    int c = tid;
    float acc[16];
    #pragma unroll
    for (int l = 0; l < 16; ++l) acc[l] = 0.f;

    const float4* w4p = (const float4*)inw + c * 16;
    #pragma unroll 1
    for (int k4 = 0; k4 < 16; ++k4) {
        float4 w = __ldg(&w4p[k4]);
        #pragma unroll
        for (int l = 0; l < 16; ++l) {
            float4 s = *(const float4*)&s_nrow[l][k4 * 4];
            acc[l] += w.x * s.x + w.y * s.y + w.z * s.z + w.w * s.w;
        }
    }
    float bb = inb[c];
    float* xzp = g_xz + ((size_t)(b * LQ + l0)) * 256 + c;
    #pragma unroll
    for (int l = 0; l < 16; ++l) xzp[(size_t)l * 256] = acc[l] + bb;
}

// ================= K2: dwconv + silu + xproj + dtproj + softplus + packing =================
// grid: B * (L/32) = 256 blocks, 256 threads, dynamic smem (~59 KB, phased aliasing).
// floats: XIN@0(47*128) CONVW@6016(2048) | XW@0(68*128) DBC@8704(32*69) | XC@10912(32*132)
#define K2_SMEM_FLOATS 15136
#define K2_SMEM_BYTES  (K2_SMEM_FLOATS * 4)

__global__ void __launch_bounds__(256) k2_conv_xproj(
    const float* __restrict__ convw,
    const float* __restrict__ convb,
    const float* __restrict__ xprojw,
    const float* __restrict__ dtw,
    const float* __restrict__ dtb,
    const float* __restrict__ Dpw)
{
    extern __shared__ float sm[];
    float* s_xin   = sm;
    float* s_convw = sm + 47 * 128;
    float* s_xw    = sm;
    float* s_dbc   = sm + 68 * 128;
    float* s_xc    = sm + 10912;

    int b  = blockIdx.x >> 6;
    int l0 = (blockIdx.x & 63) << 5;
    int tid = threadIdx.x;

    for (int i = tid; i < 128 * 16; i += 256) s_convw[i] = convw[i];
    for (int i = tid; i < 47 * 128; i += 256) {
        int r = i >> 7, ch = i & 127;
        int l = l0 - 15 + r;
        s_xin[i] = (l >= 0) ? g_xz[((size_t)(b * LQ + l)) * 256 + ch] : 0.f;
    }
    __syncthreads();

    // causal depthwise conv + silu -> s_xc
    for (int i = tid; i < 32 * 128; i += 256) {
        int l = i >> 7, ch = i & 127;
        float acc = convb[ch];
        #pragma unroll
        for (int j = 0; j < DCV; ++j)
            acc += s_convw[ch * DCV + j] * s_xin[(l + j) * 128 + ch];
        float sg = 1.f / (1.f + __expf(-acc));
        s_xc[l * 132 + ch] = acc * sg;
    }
    __syncthreads();

    for (int i = tid; i < 68 * 128; i += 256) s_xw[i] = xprojw[i];
    __syncthreads();

    // dbc GEMM: warp = r-group (9 rows), lane = l
    {
        int l = tid & 31, rg = tid >> 5;
        if (rg * 9 < RQ) {
            float acc[9];
            #pragma unroll
            for (int r = 0; r < 9; ++r) acc[r] = 0.f;
            const float4* xc4 = (const float4*)(s_xc + l * 132);
            #pragma unroll 1
            for (int kc = 0; kc < 4; ++kc) {
                float4 xr[8];
                #pragma unroll
                for (int q = 0; q < 8; ++q) xr[q] = xc4[kc * 8 + q];
                #pragma unroll
                for (int rr = 0; rr < 9; ++rr) {
                    int r = rg * 9 + rr;
                    if (r < RQ) {
                        const float4* w4 = (const float4*)(s_xw + r * 128 + kc * 32);
                        float a = acc[rr];
                        #pragma unroll
                        for (int q = 0; q < 8; ++q) {
                            float4 w = w4[q];
                            a += w.x * xr[q].x + w.y * xr[q].y + w.z * xr[q].z + w.w * xr[q].w;
                        }
                        acc[rr] = a;
                    }
                }
            }
            #pragma unroll
            for (int rr = 0; rr < 9; ++rr) {
                int r = rg * 9 + rr;
                if (r < RQ) s_dbc[l * 69 + r] = acc[rr];
            }
        }
    }
    __syncthreads();

    // dtproj + softplus + pack scan operands
    for (int i = tid; i < 32 * 128; i += 256) {
        int l = i >> 7, e = i & 127;
        const float* dr = s_dbc + l * 69;
        float4 wv = *(const float4*)(dtw + e * 4);
        float v = dr[0] * wv.x + dr[1] * wv.y + dr[2] * wv.z + dr[3] * wv.w + dtb[e];
        float delta = (v > 20.f) ? v : log1pf(__expf(v));
        float xcv = s_xc[l * 132 + e];
        float z  = g_xz[((size_t)(b * LQ + l0 + l)) * 256 + 128 + e];
        float gz = z / (1.f + __expf(-z));
        size_t oidx = ((size_t)(b * LQ + l0 + l)) * 128 + e;
        g_dx[oidx]   = make_float2(delta, delta * xcv);
        g_gate[oidx] = make_float2(gz, Dpw[e] * xcv * gz);
    }
    // pack B, C
    for (int i = tid; i < 32 * 32; i += 256) {
        int l = i >> 5, n = i & 31;
        const float* dr = s_dbc + l * 69;
        size_t oidx = ((size_t)(b * LQ + l0 + l)) * 32 + n;
        g_bB[oidx] = dr[DTR + n];
        g_bC[oidx] = dr[DTR + NQ + n];
    }
}

// ================= K3a: local chunk scan (carry out) =================
// grid: b(4) x chunk(32) x egroup(8) = 1024 blocks; 512 threads = 16 warps = 16 e's.
__global__ void __launch_bounds__(512) k3a_scan_local(const float* __restrict__ Alog)
{
    __shared__ float s_b[CH * NQ];   // 8 KB

    int eg = blockIdx.x & 7;
    int c  = (blockIdx.x >> 3) & 31;
    int b  = blockIdx.x >> 8;
    int tid = threadIdx.x, lane = tid & 31, w = tid >> 5;
    int e = eg * EG + w;

    const float* bsrc = g_bB + ((size_t)(b * LQ) + c * CH) * NQ;
    for (int i = tid; i < CH * NQ; i += 512) s_b[i] = bsrc[i];
    __syncthreads();

    float aA = -__expf(Alog[e * NQ + lane]) * LOG2EF;
    const float2* dxp = g_dx + ((size_t)(b * LQ) + c * CH) * ED + e;

    float h = 0.f, P = 1.f;
    #pragma unroll 8
    for (int j = 0; j < CH; ++j) {
        float2 m = __ldg(dxp + (size_t)j * ED);   // broadcast
        float dA = ex2(m.x * aA);
        h = fmaf(dA, h, m.y * s_b[j * NQ + lane]);
        P *= dA;
    }
    g_carry[(((size_t)(b * ED + e)) * NCH + c) * NQ + lane] = make_float2(h, P);
}

// ================= K3c: combine prologue + rescan + multi-reduce + gate =================
__global__ void __launch_bounds__(512) k3c_scan_out(const float* __restrict__ Alog)
{
    __shared__ float s_b[CH * NQ];
    __shared__ float s_c[CH * NQ];

    int eg = blockIdx.x & 7;
    int c  = (blockIdx.x >> 3) & 31;
    int b  = blockIdx.x >> 8;
    int tid = threadIdx.x, lane = tid & 31, w = tid >> 5;
    int e = eg * EG + w;

    {
        const float* bsrc = g_bB + ((size_t)(b * LQ) + c * CH) * NQ;
        const float* csrc = g_bC + ((size_t)(b * LQ) + c * CH) * NQ;
        for (int i = tid; i < CH * NQ; i += 512) { s_b[i] = bsrc[i]; s_c[i] = csrc[i]; }
    }

    // prologue: exclusive combine of carries for chunks < c (this thread = (e,lane))
    float h = 0.f;
    if (c > 0) {
        const float2* cp = g_carry + (((size_t)(b * ED + e)) * NCH) * NQ + lane;
        #pragma unroll 4
        for (int cc = 0; cc < c; ++cc) {
            float2 v = __ldg(cp + (size_t)cc * NQ);
            h = fmaf(v.y, h, v.x);
        }
    }
    __syncthreads();

    float aA = -__expf(Alog[e * NQ + lane]) * LOG2EF;
    const float2* dxp = g_dx   + ((size_t)(b * LQ) + c * CH) * ED + e;
    const float2* gtp = g_gate + ((size_t)(b * LQ) + c * CH) * ED + e;
    float* yp = g_yout + ((size_t)(b * ED + e)) * LQ + c * CH;

    for (int t0 = 0; t0 < CH; t0 += 32) {
        float v[32];
        #pragma unroll
        for (int j = 0; j < 32; ++j) {
            float2 m = __ldg(dxp + (size_t)(t0 + j) * ED);
            float dA = ex2(m.x * aA);
            h = fmaf(dA, h, m.y * s_b[(t0 + j) * NQ + lane]);
            v[j] = h * s_c[(t0 + j) * NQ + lane];
        }
        // butterfly-transpose multi-reduce: lane L ends with sum for step t0+L in v[0]
        #pragma unroll
        for (int d = 16; d >= 1; d >>= 1) {
            #pragma unroll
            for (int j = 0; j < d; ++j) {
                float send  = (lane & d) ? v[j] : v[j + d];
                float other = __shfl_xor_sync(~0u, send, d);
                float keep  = (lane & d) ? v[j + d] : v[j];
                v[j] = keep + other;
            }
        }
        float2 g = __ldg(gtp + (size_t)(t0 + lane) * ED);
        yp[t0 + lane] = fmaf(v[0], g.x, g.y);
    }
}

// ================= K4: out_proj + residual =================
__global__ void __launch_bounds__(256) k4_outproj(
    const float* __restrict__ ow,   // (64, 128)
    const float* __restrict__ ob,   // (64)
    const float* __restrict__ hin,
    float* __restrict__ hout)
{
    __shared__ float s_y[16 * 132];

    int b  = blockIdx.x >> 7;
    int l0 = (blockIdx.x & 127) << 4;
    int tid = threadIdx.x;

    for (int i = tid; i < 128 * 16; i += 256) {
        int e = i >> 4, lc = i & 15;
        s_y[lc * 132 + e] = g_yout[((size_t)(b * 128 + e)) * LQ + l0 + lc];
    }
    __syncthreads();

    int d = tid & 63, lg = tid >> 6;
    float a0 = 0.f, a1 = 0.f, a2 = 0.f, a3 = 0.f;

    const float4* wp = (const float4*)(ow + d * 128);
    const float4* y0 = (const float4*)(s_y + (lg * 4 + 0) * 132);
    const float4* y1 = (const float4*)(s_y + (lg * 4 + 1) * 132);
    const float4* y2 = (const float4*)(s_y + (lg * 4 + 2) * 132);
    const float4* y3 = (const float4*)(s_y + (lg * 4 + 3) * 132);

    #pragma unroll 8
    for (int k4 = 0; k4 < 32; ++k4) {
        float4 w = __ldg(&wp[k4]);
        float4 v0 = y0[k4], v1 = y1[k4], v2 = y2[k4], v3 = y3[k4];
        a0 += w.x * v0.x + w.y * v0.y + w.z * v0.z + w.w * v0.w;
        a1 += w.x * v1.x + w.y * v1.y + w.z * v1.z + w.w * v1.w;
        a2 += w.x * v2.x + w.y * v2.y + w.z * v2.z + w.w * v2.w;
        a3 += w.x * v3.x + w.y * v3.y + w.z * v3.z + w.w * v3.w;
    }

    float bias = ob[d];
    size_t rbase = ((size_t)(b * LQ + l0 + lg * 4)) * DM + d;
    hout[rbase + 0 * DM] = hin[rbase + 0 * DM] + bias + a0;
    hout[rbase + 1 * DM] = hin[rbase + 1 * DM] + bias + a1;
    hout[rbase + 2 * DM] = hin[rbase + 2 * DM] + bias + a2;
    hout[rbase + 3 * DM] = hin[rbase + 3 * DM] + bias + a3;
}

// ================= final classifier head =================
__global__ void __launch_bounds__(128) k_final(
    const float* __restrict__ fcw, const float* __restrict__ fcb, float* __restrict__ out)
{
    int b = threadIdx.x >> 5, lane = threadIdx.x & 31;
    float s = 0.f;
    #pragma unroll
    for (int j = 0; j < 4; ++j) {
        int e = lane + 32 * j;
        s += g_yout[((size_t)(b * 128 + e)) * LQ + (LQ - 1)] * fcw[e];
    }
    #pragma unroll
    for (int d = 16; d; d >>= 1) s += __shfl_xor_sync(~0u, s, d);
    if (lane == 0) out[b] = s + fcb[0];
}

// ================= launch =================
extern "C" void kernel_launch(void* const* d_in, const int* in_sizes, int n_in,
                              void* d_out, int out_size)
{
    const float* x        = (const float*)d_in[0];
    const float* in_w     = (const float*)d_in[1];
    const float* in_b     = (const float*)d_in[2];
    const float* conv_w   = (const float*)d_in[3];
    const float* conv_b   = (const float*)d_in[4];
    const float* xproj_w  = (const float*)d_in[5];
    const float* dtproj_w = (const float*)d_in[6];
    const float* dtproj_b = (const float*)d_in[7];
    const float* A_log    = (const float*)d_in[8];
    const float* Dp       = (const float*)d_in[9];
    const float* outp_w   = (const float*)d_in[10];
    const float* outp_b   = (const float*)d_in[11];
    const float* norm_w   = (const float*)d_in[12];
    const float* fc_w     = (const float*)d_in[13];
    const float* fc_b     = (const float*)d_in[14];
    float* out = (float*)d_out;

    (void)in_sizes; (void)n_in; (void)out_size;

    cudaFuncSetAttribute(k2_conv_xproj, cudaFuncAttributeMaxDynamicSharedMemorySize, K2_SMEM_BYTES);

    float* gh = nullptr;
    cudaGetSymbolAddress((void**)&gh, g_h);

    for (int i = 0; i < 4; ++i) {
        const float* hin = (i == 0) ? x : gh;
        k1_rms_inproj<<<512, 256>>>(hin,
                                    in_w + (size_t)i * 2 * ED * DM,
                                    in_b + (size_t)i * 2 * ED,
                                    norm_w + (size_t)i * DM);
        k2_conv_xproj<<<256, 256, K2_SMEM_BYTES>>>(
            conv_w   + (size_t)i * ED * DCV,
            conv_b   + (size_t)i * ED,
            xproj_w  + (size_t)i * RQ * ED,
            dtproj_w + (size_t)i * ED * DTR,
            dtproj_b + (size_t)i * ED,
            Dp       + (size_t)i * ED);
        const float* Al = A_log + (size_t)i * ED * NQ;
        k3a_scan_local<<<1024, 512>>>(Al);
        k3c_scan_out<<<1024, 512>>>(Al);
        if (i < 3)
            k4_outproj<<<512, 256>>>(
                outp_w + (size_t)i * DM * ED,
                outp_b + (size_t)i * DM,
                hin, gh);
    }
    k_final<<<1, 128>>>(fc_w, fc_b, out);
}

// round 5
// speedup vs baseline: 1.2710x; 1.1000x over previous
#include <cuda_runtime.h>

#define BQ 4
#define LQ 2048
#define DM 64
#define ED 128
#define NQ 32
#define DCV 16
#define DTR 4
#define RQ 68            // DTR + 2*N
#define EPSQ 1e-5f
#define LOG2EF 1.4426950408889634f

#define CH 128           // steps per chunk
#define NCH 16           // chunks (CH*NCH = LQ)
#define EG 16            // e-channels per scan block

// ---------------- scratch (device globals; no allocation allowed) ----------------
__device__ float  g_h[BQ * LQ * DM];             // residual stream
__device__ float  g_xz[BQ * LQ * 2 * ED];        // in_proj output (b,l,2e)
__device__ float2 g_dx2[BQ * ED * LQ];           // {delta, delta*xc}  (b,e,l)
__device__ float2 g_gate2[BQ * ED * LQ];         // {silu(z), Dp*xc*silu(z)} (b,e,l)
__device__ float  g_bB[BQ * LQ * NQ];            // B (b,t,n)
__device__ float2 g_bc2[BQ * LQ * NQ];           // {B,C} (b,t,n)
__device__ float  g_yout[BQ * ED * LQ];          // gated scan output (b,e,l)
__device__ float2 g_carry[BQ * ED * NCH * NQ];   // {h_final, P}

__device__ __forceinline__ float ex2(float x) {
    float r; asm("ex2.approx.ftz.f32 %0, %1;" : "=f"(r) : "f"(x)); return r;
}

// ================= K1: rmsnorm + in_proj =================
__global__ void __launch_bounds__(256) k1_rms_inproj(
    const float* __restrict__ hin,
    const float* __restrict__ inw,   // (256, 64)
    const float* __restrict__ inb,
    const float* __restrict__ nw)
{
    __shared__ float s_nrow[16][68];

    int b  = blockIdx.x >> 7;
    int l0 = (blockIdx.x & 127) << 4;
    int tid = threadIdx.x;
    int lane = tid & 31, wid = tid >> 5;

    #pragma unroll
    for (int il = 0; il < 2; ++il) {
        int l = wid * 2 + il;
        const float* hr = hin + ((size_t)(b * LQ + l0 + l)) * DM;
        float v0 = hr[lane], v1 = hr[lane + 32];
        float ss = v0 * v0 + v1 * v1;
        #pragma unroll
        for (int s = 16; s; s >>= 1) ss += __shfl_xor_sync(~0u, ss, s);
        float r = rsqrtf(ss * (1.0f / DM) + EPSQ);
        s_nrow[l][lane]      = v0 * r * nw[lane];
        s_nrow[l][lane + 32] = v1 * r * nw[lane + 32];
    }
    __syncthreads();

    int c = tid;
    float acc[16];
    #pragma unroll
    for (int l = 0; l < 16; ++l) acc[l] = 0.f;

    const float4* w4p = (const float4*)inw + c * 16;
    #pragma unroll 1
    for (int k4 = 0; k4 < 16; ++k4) {
        float4 w = __ldg(&w4p[k4]);
        #pragma unroll
        for (int l = 0; l < 16; ++l) {
            float4 s = *(const float4*)&s_nrow[l][k4 * 4];
            acc[l] += w.x * s.x + w.y * s.y + w.z * s.z + w.w * s.w;
        }
    }
    float bb = inb[c];
    float* xzp = g_xz + ((size_t)(b * LQ + l0)) * 256 + c;
    #pragma unroll
    for (int l = 0; l < 16; ++l) xzp[(size_t)l * 256] = acc[l] + bb;
}

// ================= K2: dwconv + silu + xproj + dtproj + softplus + packing =================
// grid: B * (L/32) = 256 blocks, 256 threads, dynamic smem (~77 KB, phased aliasing).
// floats: XIN@0(47*128) CONVW@6016(2048) | XW@0(68*128) DBC@8704(32*69) | XC@10912(32*132) Z@15136(32*129)
#define K2_SMEM_FLOATS 19264
#define K2_SMEM_BYTES  (K2_SMEM_FLOATS * 4)

__global__ void __launch_bounds__(256) k2_conv_xproj(
    const float* __restrict__ convw,
    const float* __restrict__ convb,
    const float* __restrict__ xprojw,
    const float* __restrict__ dtw,
    const float* __restrict__ dtb,
    const float* __restrict__ Dpw)
{
    extern __shared__ float sm[];
    float* s_xin   = sm;
    float* s_convw = sm + 47 * 128;
    float* s_xw    = sm;
    float* s_dbc   = sm + 68 * 128;
    float* s_xc    = sm + 10912;
    float* s_z     = sm + 15136;

    int b  = blockIdx.x >> 6;
    int l0 = (blockIdx.x & 63) << 5;
    int tid = threadIdx.x;

    for (int i = tid; i < 128 * 16; i += 256) s_convw[i] = convw[i];
    for (int i = tid; i < 47 * 128; i += 256) {
        int r = i >> 7, ch = i & 127;
        int l = l0 - 15 + r;
        s_xin[i] = (l >= 0) ? g_xz[((size_t)(b * LQ + l)) * 256 + ch] : 0.f;
    }
    // stage z half (coalesced read, conflict-free padded write)
    for (int i = tid; i < 32 * 128; i += 256) {
        int l = i >> 7, ch = i & 127;
        s_z[l * 129 + ch] = g_xz[((size_t)(b * LQ + l0 + l)) * 256 + 128 + ch];
    }
    __syncthreads();

    // causal depthwise conv + silu -> s_xc
    for (int i = tid; i < 32 * 128; i += 256) {
        int l = i >> 7, ch = i & 127;
        float acc = convb[ch];
        #pragma unroll
        for (int j = 0; j < DCV; ++j)
            acc += s_convw[ch * DCV + j] * s_xin[(l + j) * 128 + ch];
        float sg = 1.f / (1.f + __expf(-acc));
        s_xc[l * 132 + ch] = acc * sg;
    }
    __syncthreads();

    for (int i = tid; i < 68 * 128; i += 256) s_xw[i] = xprojw[i];
    __syncthreads();

    // dbc GEMM: warp = r-group (9 rows), lane = l
    {
        int l = tid & 31, rg = tid >> 5;
        if (rg * 9 < RQ) {
            float acc[9];
            #pragma unroll
            for (int r = 0; r < 9; ++r) acc[r] = 0.f;
            const float4* xc4 = (const float4*)(s_xc + l * 132);
            #pragma unroll 1
            for (int kc = 0; kc < 4; ++kc) {
                float4 xr[8];
                #pragma unroll
                for (int q = 0; q < 8; ++q) xr[q] = xc4[kc * 8 + q];
                #pragma unroll
                for (int rr = 0; rr < 9; ++rr) {
                    int r = rg * 9 + rr;
                    if (r < RQ) {
                        const float4* w4 = (const float4*)(s_xw + r * 128 + kc * 32);
                        float a = acc[rr];
                        #pragma unroll
                        for (int q = 0; q < 8; ++q) {
                            float4 w = w4[q];
                            a += w.x * xr[q].x + w.y * xr[q].y + w.z * xr[q].z + w.w * xr[q].w;
                        }
                        acc[rr] = a;
                    }
                }
            }
            #pragma unroll
            for (int rr = 0; rr < 9; ++rr) {
                int r = rg * 9 + rr;
                if (r < RQ) s_dbc[l * 69 + r] = acc[rr];
            }
        }
    }
    __syncthreads();

    // dtproj + softplus + pack scan operands in (b,e,l) layout (coalesced writes)
    for (int i = tid; i < 32 * 128; i += 256) {
        int e = i >> 5, l = i & 31;
        const float* dr = s_dbc + l * 69;
        float4 wv = __ldg((const float4*)(dtw + e * 4));
        float v = dr[0] * wv.x + dr[1] * wv.y + dr[2] * wv.z + dr[3] * wv.w + dtb[e];
        float delta = (v > 20.f) ? v : log1pf(__expf(v));
        float xcv = s_xc[l * 132 + e];
        float z  = s_z[l * 129 + e];
        float gz = z / (1.f + __expf(-z));
        size_t oidx = ((size_t)(b * ED + e)) * LQ + l0 + l;
        g_dx2[oidx]   = make_float2(delta, delta * xcv);
        g_gate2[oidx] = make_float2(gz, Dpw[e] * xcv * gz);
    }
    // pack B, C (b,t,n) layout
    for (int i = tid; i < 32 * 32; i += 256) {
        int l = i >> 5, n = i & 31;
        const float* dr = s_dbc + l * 69;
        size_t oidx = ((size_t)(b * LQ + l0 + l)) * 32 + n;
        float Bv = dr[DTR + n], Cv = dr[DTR + NQ + n];
        g_bB[oidx]  = Bv;
        g_bc2[oidx] = make_float2(Bv, Cv);
    }
}

// ================= K3a: local chunk scan (carry out) =================
// grid: b(4) x chunk(16) x egroup(8) = 512 blocks; 512 threads = 16 warps = 16 e's.
__global__ void __launch_bounds__(512) k3a_scan_local(const float* __restrict__ Alog)
{
    __shared__ float  s_b[CH * NQ];        // 16 KB
    __shared__ float2 s_dx[EG][CH];        // 16 KB

    int eg = blockIdx.x & 7;
    int c  = (blockIdx.x >> 3) & 15;
    int b  = blockIdx.x >> 7;
    int tid = threadIdx.x, lane = tid & 31, w = tid >> 5;
    int e = eg * EG + w;

    const float* bsrc = g_bB + ((size_t)(b * LQ) + c * CH) * NQ;
    for (int i = tid; i < CH * NQ; i += 512) s_b[i] = bsrc[i];
    {
        const float2* dsrc = g_dx2 + ((size_t)(b * ED + e)) * LQ + c * CH;
        #pragma unroll
        for (int k = 0; k < CH / 32; ++k) s_dx[w][k * 32 + lane] = __ldg(dsrc + k * 32 + lane);
    }
    __syncthreads();

    float aA = -__expf(Alog[e * NQ + lane]) * LOG2EF;

    float h = 0.f, P = 1.f;
    #pragma unroll 8
    for (int j = 0; j < CH; ++j) {
        float2 m = s_dx[w][j];
        float dA = ex2(m.x * aA);
        h = fmaf(dA, h, m.y * s_b[j * NQ + lane]);
        P *= dA;
    }
    g_carry[(((size_t)(b * ED + e)) * NCH + c) * NQ + lane] = make_float2(h, P);
}

// ================= K3c: combine prologue + rescan + multi-reduce + gate =================
// dynamic smem: s_bc (CH*NQ float2 = 32KB) + s_dx (EG*CH float2 = 16KB) = 48KB
#define K3C_SMEM_BYTES ((CH * NQ + EG * CH) * 8)

__global__ void __launch_bounds__(512) k3c_scan_out(const float* __restrict__ Alog)
{
    extern __shared__ float2 sm2[];
    float2* s_bc = sm2;                 // [t][n]
    float2 (*s_dx)[CH] = (float2(*)[CH])(sm2 + CH * NQ);

    int eg = blockIdx.x & 7;
    int c  = (blockIdx.x >> 3) & 15;
    int b  = blockIdx.x >> 7;
    int tid = threadIdx.x, lane = tid & 31, w = tid >> 5;
    int e = eg * EG + w;

    {
        const float2* bsrc = g_bc2 + ((size_t)(b * LQ) + c * CH) * NQ;
        for (int i = tid; i < CH * NQ; i += 512) s_bc[i] = bsrc[i];
        const float2* dsrc = g_dx2 + ((size_t)(b * ED + e)) * LQ + c * CH;
        #pragma unroll
        for (int k = 0; k < CH / 32; ++k) s_dx[w][k * 32 + lane] = __ldg(dsrc + k * 32 + lane);
    }

    // prologue: exclusive combine of carries for chunks < c
    float h = 0.f;
    if (c > 0) {
        const float2* cp = g_carry + (((size_t)(b * ED + e)) * NCH) * NQ + lane;
        #pragma unroll 4
        for (int cc = 0; cc < c; ++cc) {
            float2 v = __ldg(cp + (size_t)cc * NQ);
            h = fmaf(v.y, h, v.x);
        }
    }
    __syncthreads();

    float aA = -__expf(Alog[e * NQ + lane]) * LOG2EF;
    const float2* gtp = g_gate2 + ((size_t)(b * ED + e)) * LQ + c * CH;
    float* yp = g_yout + ((size_t)(b * ED + e)) * LQ + c * CH;

    for (int t0 = 0; t0 < CH; t0 += 32) {
        float v[32];
        #pragma unroll
        for (int j = 0; j < 32; ++j) {
            float2 m = s_dx[w][t0 + j];
            float2 wv = s_bc[(t0 + j) * NQ + lane];
            float dA = ex2(m.x * aA);
            h = fmaf(dA, h, m.y * wv.x);
            v[j] = h * wv.y;
        }
        // butterfly-transpose multi-reduce: lane L ends with sum for step t0+L in v[0]
        #pragma unroll
        for (int d = 16; d >= 1; d >>= 1) {
            #pragma unroll
            for (int j = 0; j < d; ++j) {
                float send  = (lane & d) ? v[j] : v[j + d];
                float other = __shfl_xor_sync(~0u, send, d);
                float keep  = (lane & d) ? v[j + d] : v[j];
                v[j] = keep + other;
            }
        }
        float2 g = __ldg(gtp + t0 + lane);                 // coalesced
        yp[t0 + lane] = fmaf(v[0], g.x, g.y);
    }
}

// ================= K4: out_proj + residual =================
__global__ void __launch_bounds__(256) k4_outproj(
    const float* __restrict__ ow,   // (64, 128)
    const float* __restrict__ ob,
    const float* __restrict__ hin,
    float* __restrict__ hout)
{
    __shared__ float s_y[16 * 132];

    int b  = blockIdx.x >> 7;
    int l0 = (blockIdx.x & 127) << 4;
    int tid = threadIdx.x;

    for (int i = tid; i < 128 * 16; i += 256) {
        int e = i >> 4, lc = i & 15;
        s_y[lc * 132 + e] = g_yout[((size_t)(b * 128 + e)) * LQ + l0 + lc];
    }
    __syncthreads();

    int d = tid & 63, lg = tid >> 6;
    float a0 = 0.f, a1 = 0.f, a2 = 0.f, a3 = 0.f;

    const float4* wp = (const float4*)(ow + d * 128);
    const float4* y0 = (const float4*)(s_y + (lg * 4 + 0) * 132);
    const float4* y1 = (const float4*)(s_y + (lg * 4 + 1) * 132);
    const float4* y2 = (const float4*)(s_y + (lg * 4 + 2) * 132);
    const float4* y3 = (const float4*)(s_y + (lg * 4 + 3) * 132);

    #pragma unroll 8
    for (int k4 = 0; k4 < 32; ++k4) {
        float4 w = __ldg(&wp[k4]);
        float4 v0 = y0[k4], v1 = y1[k4], v2 = y2[k4], v3 = y3[k4];
        a0 += w.x * v0.x + w.y * v0.y + w.z * v0.z + w.w * v0.w;
        a1 += w.x * v1.x + w.y * v1.y + w.z * v1.z + w.w * v1.w;
        a2 += w.x * v2.x + w.y * v2.y + w.z * v2.z + w.w * v2.w;
        a3 += w.x * v3.x + w.y * v3.y + w.z * v3.z + w.w * v3.w;
    }

    float bias = ob[d];
    size_t rbase = ((size_t)(b * LQ + l0 + lg * 4)) * DM + d;
    hout[rbase + 0 * DM] = hin[rbase + 0 * DM] + bias + a0;
    hout[rbase + 1 * DM] = hin[rbase + 1 * DM] + bias + a1;
    hout[rbase + 2 * DM] = hin[rbase + 2 * DM] + bias + a2;
    hout[rbase + 3 * DM] = hin[rbase + 3 * DM] + bias + a3;
}

// ================= final classifier head =================
__global__ void __launch_bounds__(128) k_final(
    const float* __restrict__ fcw, const float* __restrict__ fcb, float* __restrict__ out)
{
    int b = threadIdx.x >> 5, lane = threadIdx.x & 31;
    float s = 0.f;
    #pragma unroll
    for (int j = 0; j < 4; ++j) {
        int e = lane + 32 * j;
        s += g_yout[((size_t)(b * 128 + e)) * LQ + (LQ - 1)] * fcw[e];
    }
    #pragma unroll
    for (int d = 16; d; d >>= 1) s += __shfl_xor_sync(~0u, s, d);
    if (lane == 0) out[b] = s + fcb[0];
}

// ================= launch =================
extern "C" void kernel_launch(void* const* d_in, const int* in_sizes, int n_in,
                              void* d_out, int out_size)
{
    const float* x        = (const float*)d_in[0];
    const float* in_w     = (const float*)d_in[1];
    const float* in_b     = (const float*)d_in[2];
    const float* conv_w   = (const float*)d_in[3];
    const float* conv_b   = (const float*)d_in[4];
    const float* xproj_w  = (const float*)d_in[5];
    const float* dtproj_w = (const float*)d_in[6];
    const float* dtproj_b = (const float*)d_in[7];
    const float* A_log    = (const float*)d_in[8];
    const float* Dp       = (const float*)d_in[9];
    const float* outp_w   = (const float*)d_in[10];
    const float* outp_b   = (const float*)d_in[11];
    const float* norm_w   = (const float*)d_in[12];
    const float* fc_w     = (const float*)d_in[13];
    const float* fc_b     = (const float*)d_in[14];
    float* out = (float*)d_out;

    (void)in_sizes; (void)n_in; (void)out_size;

    cudaFuncSetAttribute(k2_conv_xproj, cudaFuncAttributeMaxDynamicSharedMemorySize, K2_SMEM_BYTES);
    cudaFuncSetAttribute(k3c_scan_out,  cudaFuncAttributeMaxDynamicSharedMemorySize, K3C_SMEM_BYTES);

    float* gh = nullptr;
    cudaGetSymbolAddress((void**)&gh, g_h);

    for (int i = 0; i < 4; ++i) {
        const float* hin = (i == 0) ? x : gh;
        k1_rms_inproj<<<512, 256>>>(hin,
                                    in_w + (size_t)i * 2 * ED * DM,
                                    in_b + (size_t)i * 2 * ED,
                                    norm_w + (size_t)i * DM);
        k2_conv_xproj<<<256, 256, K2_SMEM_BYTES>>>(
            conv_w   + (size_t)i * ED * DCV,
            conv_b   + (size_t)i * ED,
            xproj_w  + (size_t)i * RQ * ED,
            dtproj_w + (size_t)i * ED * DTR,
            dtproj_b + (size_t)i * ED,
            Dp       + (size_t)i * ED);
        const float* Al = A_log + (size_t)i * ED * NQ;
        k3a_scan_local<<<512, 512>>>(Al);
        k3c_scan_out<<<512, 512, K3C_SMEM_BYTES>>>(Al);
        if (i < 3)
            k4_outproj<<<512, 256>>>(
                outp_w + (size_t)i * DM * ED,
                outp_b + (size_t)i * DM,
                hin, gh);
    }
    k_final<<<1, 128>>>(fc_w, fc_b, out);
}